// round 13
// baseline (speedup 1.0000x reference)
#include <cuda_runtime.h>
#include <cuda_bf16.h>
#include <cstdint>

// Problem constants
#define BATCH 4
#define SEQ   2048
#define DM    1024
#define NH    16
#define HD    64
#define M_ROWS (BATCH*SEQ)   // 8192

// Scratch (device globals; no allocation allowed)
__device__ float g_qkv[(size_t)M_ROWS * 3 * DM];   // [B*T, 3*C], tf32-rounded
__device__ float g_y[(size_t)M_ROWS * DM];         // [B*T, C],   tf32-rounded
__device__ float g_xr[(size_t)M_ROWS * DM];        // x rounded
__device__ float g_wq[(size_t)DM * 3 * DM];        // w_qkv rounded
__device__ float g_wp[(size_t)DM * DM];            // w_proj rounded

__device__ __forceinline__ uint32_t f2tf(float f) {
    uint32_t u;
    asm("cvt.rna.tf32.f32 %0, %1;" : "=r"(u) : "f"(f));
    return u;
}

__device__ __forceinline__ uint32_t smem_u32(const void* p) {
    uint32_t a;
    asm("{ .reg .u64 t; cvta.to.shared.u64 t, %1; cvt.u32.u64 %0, t; }"
        : "=r"(a) : "l"(p));
    return a;
}

__device__ __forceinline__ void cp16(uint32_t dst, const void* src) {
    asm volatile("cp.async.ca.shared.global [%0], [%1], 16;" :: "r"(dst), "l"(src));
}
#define CP_COMMIT() asm volatile("cp.async.commit_group;" ::: "memory")
#define CP_WAIT(n)  asm volatile("cp.async.wait_group %0;" :: "n"(n) : "memory")

#define MMA_TF32(acc, a, b0v, b1v)                                              \
    asm volatile(                                                               \
        "mma.sync.aligned.m16n8k8.row.col.f32.tf32.tf32.f32 "                   \
        "{%0,%1,%2,%3}, {%4,%5,%6,%7}, {%8,%9}, {%0,%1,%2,%3};"                 \
        : "+f"(acc[0]), "+f"(acc[1]), "+f"(acc[2]), "+f"(acc[3])                \
        : "r"(a[0]), "r"(a[1]), "r"(a[2]), "r"(a[3]), "r"(b0v), "r"(b1v))

#define LDSM_X4(r, addr)                                                        \
    asm volatile(                                                               \
        "ldmatrix.sync.aligned.m8n8.x4.shared.b16 {%0,%1,%2,%3}, [%4];"         \
        : "=r"((r)[0]), "=r"((r)[1]), "=r"((r)[2]), "=r"((r)[3])                \
        : "r"(addr))

#define TFS 136     // B smem row stride (8 mod 32 -> conflict-free quad loads)
#define AST 20      // A smem row stride (16B aligned; LDSM bank-distinct)
#define ABYTES (128 * AST * 4)   // 10240
#define BBYTES (16 * TFS * 4)    // 8704

// ---------------------------------------------------------------------------
// Pre-round: out[i] = tf32_rna(in[i]) (vectorized). n % 4 == 0.
// ---------------------------------------------------------------------------
__global__ void round_tf32_4(const float* __restrict__ in, float* __restrict__ out, int n4)
{
    int i = blockIdx.x * blockDim.x + threadIdx.x;
    if (i < n4) {
        float4 v = ((const float4*)in)[i];
        float4 o;
        o.x = __uint_as_float(f2tf(v.x));
        o.y = __uint_as_float(f2tf(v.y));
        o.z = __uint_as_float(f2tf(v.z));
        o.w = __uint_as_float(f2tf(v.w));
        ((float4*)out)[i] = o;
    }
}

// ---------------------------------------------------------------------------
// TF32 GEMM, cp.async staged, inputs pre-rounded (NO cvt in the loop).
// C[M,N] = A[M,K] @ B[K,N] + bias[N];  optional tf32-rounding of output.
// 128x128 tile, BK=16, 2-stage cp.async ring, 128 thr (4 warps 2x2),
// warp tile 64x64, A frags via ldmatrix.x4, B frags scalar (conflict-free).
// ---------------------------------------------------------------------------
__global__ __launch_bounds__(128, 2) void tf32_gemm_cp(
    const float* __restrict__ A, const float* __restrict__ B,
    const float* __restrict__ bias, float* __restrict__ C,
    int M, int N, int K, int roundOut)
{
    __shared__ uint32_t As[2][128 * AST];
    __shared__ uint32_t Bs[2][16 * TFS];

    const int tid  = threadIdx.x;
    const int lane = tid & 31;
    const int wid  = tid >> 5;
    const int gid  = lane >> 2;
    const int tig  = lane & 3;
    const int wm   = (wid & 1) * 64;
    const int wn   = (wid >> 1) * 64;
    const int bm   = blockIdx.y * 128;
    const int bn   = blockIdx.x * 128;

    // cp.async source/dest indexing
    const float* aSrc = A + (size_t)(bm + tid) * K;        // + t*16 + j*4
    const int bk  = tid >> 3;                              // 0..15
    const int bc0 = (tid & 7) * 16;                        // 0..112
    const float* bSrc = B + (size_t)bk * N + bn + bc0;     // + t*16*N + j*4

    const uint32_t aBase = smem_u32(&As[0][0]);
    const uint32_t bBase = smem_u32(&Bs[0][0]);
    const uint32_t aDst0 = aBase + (uint32_t)(tid * AST) * 4;
    const uint32_t bDst0 = bBase + (uint32_t)(bk * TFS + bc0) * 4;

    // ldmatrix base: row wm + (lane&15), k-word (lane>>4)*4
    const uint32_t aLdsm = aBase +
        (uint32_t)(((wm + (lane & 15)) * AST + ((lane >> 4) << 2)) * 4);

    float acc[4][8][4];
#pragma unroll
    for (int mt = 0; mt < 4; mt++)
#pragma unroll
        for (int nt = 0; nt < 8; nt++)
#pragma unroll
            for (int i = 0; i < 4; i++) acc[mt][nt][i] = 0.f;

    const int NT = K / 16;

#define FILL(s, t)                                                         \
    {                                                                      \
        const float* ap = aSrc + (t) * 16;                                 \
        const float* bp = bSrc + (size_t)(t) * 16 * N;                     \
        const uint32_t ad = aDst0 + (s) * ABYTES;                          \
        const uint32_t bd = bDst0 + (s) * BBYTES;                          \
        cp16(ad,      ap);      cp16(ad + 16, ap + 4);                     \
        cp16(ad + 32, ap + 8);  cp16(ad + 48, ap + 12);                    \
        cp16(bd,      bp);      cp16(bd + 16, bp + 4);                     \
        cp16(bd + 32, bp + 8);  cp16(bd + 48, bp + 12);                    \
    }

    FILL(0, 0);
    CP_COMMIT();

    for (int t = 0; t < NT; t++) {
        const int s = t & 1;
        if (t + 1 < NT) FILL((t + 1) & 1, t + 1);
        CP_COMMIT();
        CP_WAIT(1);
        __syncthreads();

        const uint32_t aStage = aLdsm + s * ABYTES;
        const uint32_t* bStage = &Bs[s][0];
#pragma unroll
        for (int kk = 0; kk < 16; kk += 8) {
            uint32_t af[4][4], bf[8][2];
            LDSM_X4(af[0], aStage + kk * 4);
            LDSM_X4(af[1], aStage + 1 * (16 * AST * 4) + kk * 4);
            LDSM_X4(af[2], aStage + 2 * (16 * AST * 4) + kk * 4);
            LDSM_X4(af[3], aStage + 3 * (16 * AST * 4) + kk * 4);
#pragma unroll
            for (int nt = 0; nt < 8; nt++) {
                const int c = wn + nt * 8 + gid;
                bf[nt][0] = bStage[(kk + tig) * TFS + c];
                bf[nt][1] = bStage[(kk + tig + 4) * TFS + c];
            }
#pragma unroll
            for (int mt = 0; mt < 4; mt++)
#pragma unroll
                for (int nt = 0; nt < 8; nt++)
                    MMA_TF32(acc[mt][nt], af[mt], bf[nt][0], bf[nt][1]);
        }
        __syncthreads();
    }

    // Epilogue with bias (optionally tf32-rounded output)
#pragma unroll
    for (int mt = 0; mt < 4; mt++) {
        const int r0 = bm + wm + mt * 16 + gid;
#pragma unroll
        for (int nt = 0; nt < 8; nt++) {
            const int col = bn + wn + nt * 8 + 2 * tig;
            const float bx = bias[col], by = bias[col + 1];
            float2 v0 = {acc[mt][nt][0] + bx, acc[mt][nt][1] + by};
            float2 v1 = {acc[mt][nt][2] + bx, acc[mt][nt][3] + by};
            if (roundOut) {
                v0.x = __uint_as_float(f2tf(v0.x));
                v0.y = __uint_as_float(f2tf(v0.y));
                v1.x = __uint_as_float(f2tf(v1.x));
                v1.y = __uint_as_float(f2tf(v1.y));
            }
            *(float2*)(C + (size_t)r0 * N + col)       = v0;
            *(float2*)(C + (size_t)(r0 + 8) * N + col) = v1;
        }
    }
}

// ---------------------------------------------------------------------------
// Tensor-core flash attention (r12 core; qkv arrives tf32-rounded -> no cvt
// on Q/K/V paths). 128 q/block, 4 warps x 32 q, P in regs via quad shfl.
// y written tf32-rounded (feeds cvt-free GEMM2).
// ---------------------------------------------------------------------------
__global__ __launch_bounds__(128) void flash_attn_tc(
    const float* __restrict__ qkv, float* __restrict__ y)
{
    __shared__ uint32_t ks[64][68];
    __shared__ uint32_t vst[64][68];

    const int tid  = threadIdx.x;
    const int lane = tid & 31;
    const int wid  = tid >> 5;
    const int gid  = lane >> 2;
    const int tig  = lane & 3;
    const int wq   = wid * 32;
    const int qt0  = (int)(gridDim.x - 1 - blockIdx.x) * 128;
    const int h    = blockIdx.y;
    const int b    = blockIdx.z;

    // Q fragments: values pre-rounded; *0.125f is exact -> still valid tf32
    uint32_t qf[2][8][4];
#pragma unroll
    for (int mt = 0; mt < 2; mt++) {
        const float* q0 = qkv + ((size_t)(b * SEQ + qt0 + wq + mt * 16 + gid) * (3 * DM)) + h * HD;
        const float* q1 = q0 + (size_t)8 * 3 * DM;
#pragma unroll
        for (int kk = 0; kk < 8; kk++) {
            qf[mt][kk][0] = __float_as_uint(q0[kk * 8 + tig]     * 0.125f);
            qf[mt][kk][1] = __float_as_uint(q1[kk * 8 + tig]     * 0.125f);
            qf[mt][kk][2] = __float_as_uint(q0[kk * 8 + tig + 4] * 0.125f);
            qf[mt][kk][3] = __float_as_uint(q1[kk * 8 + tig + 4] * 0.125f);
        }
    }

    float o[2][8][4];
#pragma unroll
    for (int mt = 0; mt < 2; mt++)
#pragma unroll
        for (int nt = 0; nt < 8; nt++) {
            o[mt][nt][0] = 0.f; o[mt][nt][1] = 0.f;
            o[mt][nt][2] = 0.f; o[mt][nt][3] = 0.f;
        }
    float m[2][2] = {{-1e30f, -1e30f}, {-1e30f, -1e30f}};
    float l[2][2] = {{0.f, 0.f}, {0.f, 0.f}};

    const int ntiles = qt0 / 64 + 2;
    const int krow = tid & 63;
    const int kcb  = (tid >> 6) * 32;

    const int src0 = tig >> 1;
    const int src2 = (tig >> 1) + 2;
    const bool sel = (tig & 1);

    for (int kt = 0; kt < ntiles; kt++) {
        const int kt0 = kt * 64;

        __syncthreads();
        {
            const float* kp = qkv + ((size_t)(b * SEQ + kt0 + krow) * (3 * DM)) + DM + h * HD + kcb;
            const float* vp = kp + DM;
#pragma unroll
            for (int j = 0; j < 32; j += 4) {
                uint4 k4 = *(const uint4*)(kp + j);   // bits already tf32
                uint4 v4 = *(const uint4*)(vp + j);
                *(uint4*)&ks[krow][kcb + j] = k4;
                vst[kcb + j + 0][krow] = v4.x;
                vst[kcb + j + 1][krow] = v4.y;
                vst[kcb + j + 2][krow] = v4.z;
                vst[kcb + j + 3][krow] = v4.w;
            }
        }
        __syncthreads();

        if (kt0 > qt0 + wq + 31) continue;

        float acc[2][8][4];
#pragma unroll
        for (int mt = 0; mt < 2; mt++)
#pragma unroll
            for (int nt = 0; nt < 8; nt++) {
                acc[mt][nt][0] = 0.f; acc[mt][nt][1] = 0.f;
                acc[mt][nt][2] = 0.f; acc[mt][nt][3] = 0.f;
            }
#pragma unroll
        for (int kk = 0; kk < 8; kk++) {
            uint32_t bf0[8], bf1[8];
#pragma unroll
            for (int nt = 0; nt < 8; nt++) {
                bf0[nt] = ks[nt * 8 + gid][kk * 8 + tig];
                bf1[nt] = ks[nt * 8 + gid][kk * 8 + tig + 4];
            }
#pragma unroll
            for (int mt = 0; mt < 2; mt++)
#pragma unroll
                for (int nt = 0; nt < 8; nt++)
                    MMA_TF32(acc[mt][nt], qf[mt][kk], bf0[nt], bf1[nt]);
        }

#pragma unroll
        for (int mt = 0; mt < 2; mt++) {
            if (kt0 + 63 > qt0 + wq + mt * 16) {
                const int r0 = qt0 + wq + mt * 16 + gid, r1 = r0 + 8;
#pragma unroll
                for (int nt = 0; nt < 8; nt++) {
                    const int c = kt0 + nt * 8 + 2 * tig;
                    if (c     > r0) acc[mt][nt][0] = -1e30f;
                    if (c + 1 > r0) acc[mt][nt][1] = -1e30f;
                    if (c     > r1) acc[mt][nt][2] = -1e30f;
                    if (c + 1 > r1) acc[mt][nt][3] = -1e30f;
                }
            }
        }

#pragma unroll
        for (int mt = 0; mt < 2; mt++) {
            float mt0 = -1e30f, mt1 = -1e30f;
#pragma unroll
            for (int nt = 0; nt < 8; nt++) {
                mt0 = fmaxf(mt0, fmaxf(acc[mt][nt][0], acc[mt][nt][1]));
                mt1 = fmaxf(mt1, fmaxf(acc[mt][nt][2], acc[mt][nt][3]));
            }
            mt0 = fmaxf(mt0, __shfl_xor_sync(0xffffffffu, mt0, 1));
            mt0 = fmaxf(mt0, __shfl_xor_sync(0xffffffffu, mt0, 2));
            mt1 = fmaxf(mt1, __shfl_xor_sync(0xffffffffu, mt1, 1));
            mt1 = fmaxf(mt1, __shfl_xor_sync(0xffffffffu, mt1, 2));

            const float mn0 = fmaxf(m[mt][0], mt0), mn1 = fmaxf(m[mt][1], mt1);
            const float cr0 = __expf(m[mt][0] - mn0), cr1 = __expf(m[mt][1] - mn1);
            m[mt][0] = mn0; m[mt][1] = mn1;
            l[mt][0] *= cr0; l[mt][1] *= cr1;

            float s0 = 0.f, s1 = 0.f;
#pragma unroll
            for (int nt = 0; nt < 8; nt++) {
                const float p0 = __expf(acc[mt][nt][0] - mn0);
                const float p1 = __expf(acc[mt][nt][1] - mn0);
                const float p2 = __expf(acc[mt][nt][2] - mn1);
                const float p3 = __expf(acc[mt][nt][3] - mn1);
                s0 += p0 + p1;
                s1 += p2 + p3;
                o[mt][nt][0] *= cr0; o[mt][nt][1] *= cr0;
                o[mt][nt][2] *= cr1; o[mt][nt][3] *= cr1;
                acc[mt][nt][0] = __uint_as_float(f2tf(p0));
                acc[mt][nt][1] = __uint_as_float(f2tf(p1));
                acc[mt][nt][2] = __uint_as_float(f2tf(p2));
                acc[mt][nt][3] = __uint_as_float(f2tf(p3));
            }
            s0 += __shfl_xor_sync(0xffffffffu, s0, 1);
            s0 += __shfl_xor_sync(0xffffffffu, s0, 2);
            s1 += __shfl_xor_sync(0xffffffffu, s1, 1);
            s1 += __shfl_xor_sync(0xffffffffu, s1, 2);
            l[mt][0] += s0; l[mt][1] += s1;
        }

#pragma unroll
        for (int kk = 0; kk < 8; kk++) {
            uint32_t pa[2][4];
#pragma unroll
            for (int mt = 0; mt < 2; mt++) {
                const uint32_t e0 = __float_as_uint(acc[mt][kk][0]);
                const uint32_t e1 = __float_as_uint(acc[mt][kk][1]);
                const uint32_t e2 = __float_as_uint(acc[mt][kk][2]);
                const uint32_t e3 = __float_as_uint(acc[mt][kk][3]);
                const uint32_t u0 = __shfl_sync(0xffffffffu, e0, src0, 4);
                const uint32_t u1 = __shfl_sync(0xffffffffu, e1, src0, 4);
                pa[mt][0] = sel ? u1 : u0;
                const uint32_t v0 = __shfl_sync(0xffffffffu, e2, src0, 4);
                const uint32_t v1 = __shfl_sync(0xffffffffu, e3, src0, 4);
                pa[mt][1] = sel ? v1 : v0;
                const uint32_t w0 = __shfl_sync(0xffffffffu, e0, src2, 4);
                const uint32_t w1 = __shfl_sync(0xffffffffu, e1, src2, 4);
                pa[mt][2] = sel ? w1 : w0;
                const uint32_t x0 = __shfl_sync(0xffffffffu, e2, src2, 4);
                const uint32_t x1 = __shfl_sync(0xffffffffu, e3, src2, 4);
                pa[mt][3] = sel ? x1 : x0;
            }
#pragma unroll
            for (int nt = 0; nt < 8; nt++) {
                const uint32_t b0 = vst[nt * 8 + gid][kk * 8 + tig];
                const uint32_t b1 = vst[nt * 8 + gid][kk * 8 + tig + 4];
#pragma unroll
                for (int mt = 0; mt < 2; mt++)
                    MMA_TF32(o[mt][nt], pa[mt], b0, b1);
            }
        }
    }

    // Epilogue: normalize, tf32-round (GEMM2 input), write
#pragma unroll
    for (int mt = 0; mt < 2; mt++) {
        const float i0 = 1.f / l[mt][0], i1 = 1.f / l[mt][1];
        float* y0 = y + (size_t)(b * SEQ + qt0 + wq + mt * 16 + gid) * DM + h * HD;
        float* y1 = y0 + (size_t)8 * DM;
#pragma unroll
        for (int nt = 0; nt < 8; nt++) {
            const int c = nt * 8 + 2 * tig;
            float2 w0, w1;
            w0.x = __uint_as_float(f2tf(o[mt][nt][0] * i0));
            w0.y = __uint_as_float(f2tf(o[mt][nt][1] * i0));
            w1.x = __uint_as_float(f2tf(o[mt][nt][2] * i1));
            w1.y = __uint_as_float(f2tf(o[mt][nt][3] * i1));
            *(float2*)(y0 + c) = w0;
            *(float2*)(y1 + c) = w1;
        }
    }
}

// ---------------------------------------------------------------------------
// Launch
// ---------------------------------------------------------------------------
extern "C" void kernel_launch(void* const* d_in, const int* in_sizes, int n_in,
                              void* d_out, int out_size)
{
    (void)in_sizes; (void)n_in; (void)out_size;
    const float* x      = (const float*)d_in[0];
    const float* w_qkv  = (const float*)d_in[1];
    const float* b_qkv  = (const float*)d_in[2];
    const float* w_proj = (const float*)d_in[3];
    const float* b_proj = (const float*)d_in[4];
    float* out = (float*)d_out;

    float *qkv, *y, *xr, *wq, *wp;
    cudaGetSymbolAddress((void**)&qkv, g_qkv);
    cudaGetSymbolAddress((void**)&y,   g_y);
    cudaGetSymbolAddress((void**)&xr,  g_xr);
    cudaGetSymbolAddress((void**)&wq,  g_wq);
    cudaGetSymbolAddress((void**)&wp,  g_wp);

    // 0) Pre-round inputs to tf32 (idempotent with in-loop cvt => same math)
    round_tf32_4<<<(M_ROWS * DM / 4 + 255) / 256, 256>>>(x, xr, M_ROWS * DM / 4);
    round_tf32_4<<<(DM * 3 * DM / 4 + 255) / 256, 256>>>(w_qkv, wq, DM * 3 * DM / 4);
    round_tf32_4<<<(DM * DM / 4 + 255) / 256, 256>>>(w_proj, wp, DM * DM / 4);

    // 1) QKV projection (output tf32-rounded for attention)
    tf32_gemm_cp<<<dim3(3 * DM / 128, M_ROWS / 128), 128>>>(
        xr, wq, b_qkv, qkv, M_ROWS, 3 * DM, DM, 1);

    // 2) Causal flash attention (cvt-free loads; y written rounded)
    flash_attn_tc<<<dim3(SEQ / 128, NH, BATCH), 128>>>(qkv, y);

    // 3) Output projection (final output NOT rounded)
    tf32_gemm_cp<<<dim3(DM / 128, M_ROWS / 128), 128>>>(
        y, wp, b_proj, out, M_ROWS, DM, DM, 0);
}

// round 15
// speedup vs baseline: 1.1750x; 1.1750x over previous
#include <cuda_runtime.h>
#include <cuda_bf16.h>
#include <cstdint>

// Problem constants
#define BATCH 4
#define SEQ   2048
#define DM    1024
#define NH    16
#define HD    64
#define M_ROWS (BATCH*SEQ)   // 8192

// Scratch (device globals; no allocation allowed)
__device__ float g_qkv[(size_t)M_ROWS * 3 * DM];   // [B*T, 3*C] (sel, head, hd)
__device__ float g_y[(size_t)M_ROWS * DM];         // [B*T, C]

__device__ __forceinline__ uint32_t f2tf(float f) {
    uint32_t u;
    asm("cvt.rna.tf32.f32 %0, %1;" : "=r"(u) : "f"(f));
    return u;
}

__device__ __forceinline__ uint32_t smem_u32(const void* p) {
    uint32_t a;
    asm("{ .reg .u64 t; cvta.to.shared.u64 t, %1; cvt.u32.u64 %0, t; }"
        : "=r"(a) : "l"(p));
    return a;
}

#define MMA_TF32(acc, a, b0v, b1v)                                              \
    asm volatile(                                                               \
        "mma.sync.aligned.m16n8k8.row.col.f32.tf32.tf32.f32 "                   \
        "{%0,%1,%2,%3}, {%4,%5,%6,%7}, {%8,%9}, {%0,%1,%2,%3};"                 \
        : "+f"(acc[0]), "+f"(acc[1]), "+f"(acc[2]), "+f"(acc[3])                \
        : "r"(a[0]), "r"(a[1]), "r"(a[2]), "r"(a[3]), "r"(b0v), "r"(b1v))

// Variant taking 4 explicit A regs (for P-as-A-fragment renaming)
#define MMA_TF32_A4(acc, a0, a1, a2, a3, b0v, b1v)                              \
    asm volatile(                                                               \
        "mma.sync.aligned.m16n8k8.row.col.f32.tf32.tf32.f32 "                   \
        "{%0,%1,%2,%3}, {%4,%5,%6,%7}, {%8,%9}, {%0,%1,%2,%3};"                 \
        : "+f"(acc[0]), "+f"(acc[1]), "+f"(acc[2]), "+f"(acc[3])                \
        : "r"(a0), "r"(a1), "r"(a2), "r"(a3), "r"(b0v), "r"(b1v))

#define LDSM_X4(r, addr)                                                        \
    asm volatile(                                                               \
        "ldmatrix.sync.aligned.m8n8.x4.shared.b16 {%0,%1,%2,%3}, [%4];"         \
        : "=r"((r)[0]), "=r"((r)[1]), "=r"((r)[2]), "=r"((r)[3])                \
        : "r"(addr))

#define TFS 136   // B smem row stride (8 mod 32 -> conflict-free quad frag loads)
#define AST 20    // A smem row stride (16B aligned; LDSM bank-distinct)

// ---------------------------------------------------------------------------
// TF32 GEMM with bias (r12, measured best 415.7us): 128x128 tile, BK=16
// double-buffered, 128 thr (4 warps 2x2), warp tile 64x64, 2 CTAs/SM.
// A frags via ldmatrix.x4, B frags scalar (conflict-free). cvt at store.
// ---------------------------------------------------------------------------
__global__ __launch_bounds__(128, 2) void tf32_gemm_bias(
    const float* __restrict__ A, const float* __restrict__ B,
    const float* __restrict__ bias, float* __restrict__ C,
    int M, int N, int K)
{
    __shared__ uint32_t As[2][128][AST];   // [buf][row][k]  (10240 B per buf)
    __shared__ uint32_t Bs[2][16][TFS];    // [buf][k][col]

    const int tid  = threadIdx.x;
    const int lane = tid & 31;
    const int wid  = tid >> 5;
    const int gid  = lane >> 2;
    const int tig  = lane & 3;
    const int wm   = (wid & 1) * 64;
    const int wn   = (wid >> 1) * 64;
    const int bm   = blockIdx.y * 128;
    const int bn   = blockIdx.x * 128;

    const int br = tid >> 4;          // 0..7
    const int bc = (tid & 15) * 4;    // 0..60

    const float* Ap = A + (size_t)(bm + tid) * K;
    const float* Bp = B + (size_t)br * N + bn + bc;

    const uint32_t aLdsm = smem_u32(&As[0][0][0]) +
        (uint32_t)(((wm + (lane & 15)) * AST + ((lane >> 4) << 2)) * 4);

    float acc[4][8][4];
#pragma unroll
    for (int mt = 0; mt < 4; mt++)
#pragma unroll
        for (int nt = 0; nt < 8; nt++)
#pragma unroll
            for (int i = 0; i < 4; i++) acc[mt][nt][i] = 0.f;

    const int ntiles = K / 16;
    float4 pa[4], pb[4];

    // Preload tile 0 -> buf 0
    {
#pragma unroll
        for (int j = 0; j < 4; j++) pa[j] = ((const float4*)Ap)[j];
        pb[0] = *(const float4*)(Bp);
        pb[1] = *(const float4*)(Bp + 64);
        pb[2] = *(const float4*)(Bp + (size_t)8 * N);
        pb[3] = *(const float4*)(Bp + (size_t)8 * N + 64);
#pragma unroll
        for (int j = 0; j < 4; j++) {
            uint4 w;
            w.x = f2tf(pa[j].x); w.y = f2tf(pa[j].y);
            w.z = f2tf(pa[j].z); w.w = f2tf(pa[j].w);
            *(uint4*)&As[0][tid][j * 4] = w;
        }
        Bs[0][br][bc + 0]      = f2tf(pb[0].x);
        Bs[0][br][bc + 1]      = f2tf(pb[0].y);
        Bs[0][br][bc + 2]      = f2tf(pb[0].z);
        Bs[0][br][bc + 3]      = f2tf(pb[0].w);
        Bs[0][br][bc + 64]     = f2tf(pb[1].x);
        Bs[0][br][bc + 65]     = f2tf(pb[1].y);
        Bs[0][br][bc + 66]     = f2tf(pb[1].z);
        Bs[0][br][bc + 67]     = f2tf(pb[1].w);
        Bs[0][br + 8][bc + 0]  = f2tf(pb[2].x);
        Bs[0][br + 8][bc + 1]  = f2tf(pb[2].y);
        Bs[0][br + 8][bc + 2]  = f2tf(pb[2].z);
        Bs[0][br + 8][bc + 3]  = f2tf(pb[2].w);
        Bs[0][br + 8][bc + 64] = f2tf(pb[3].x);
        Bs[0][br + 8][bc + 65] = f2tf(pb[3].y);
        Bs[0][br + 8][bc + 66] = f2tf(pb[3].z);
        Bs[0][br + 8][bc + 67] = f2tf(pb[3].w);
    }
    __syncthreads();

    int buf = 0;
    for (int t = 0; t < ntiles; t++) {
        if (t + 1 < ntiles) {
            const int k0 = (t + 1) * 16;
            const float* ap = Ap + k0;
            const float* bp = Bp + (size_t)k0 * N;
#pragma unroll
            for (int j = 0; j < 4; j++) pa[j] = ((const float4*)ap)[j];
            pb[0] = *(const float4*)(bp);
            pb[1] = *(const float4*)(bp + 64);
            pb[2] = *(const float4*)(bp + (size_t)8 * N);
            pb[3] = *(const float4*)(bp + (size_t)8 * N + 64);
        }

        const uint32_t aBufAddr = aLdsm + (uint32_t)(buf * 10240);
#pragma unroll
        for (int kk = 0; kk < 16; kk += 8) {
            uint32_t af[4][4], bf[8][2];
            LDSM_X4(af[0], aBufAddr + kk * 4);
            LDSM_X4(af[1], aBufAddr + 1 * 1280 + kk * 4);
            LDSM_X4(af[2], aBufAddr + 2 * 1280 + kk * 4);
            LDSM_X4(af[3], aBufAddr + 3 * 1280 + kk * 4);
#pragma unroll
            for (int nt = 0; nt < 8; nt++) {
                const int c = wn + nt * 8 + gid;
                bf[nt][0] = Bs[buf][kk + tig][c];
                bf[nt][1] = Bs[buf][kk + tig + 4][c];
            }
#pragma unroll
            for (int mt = 0; mt < 4; mt++)
#pragma unroll
                for (int nt = 0; nt < 8; nt++)
                    MMA_TF32(acc[mt][nt], af[mt], bf[nt][0], bf[nt][1]);
        }

        if (t + 1 < ntiles) {
            const int nb = buf ^ 1;
#pragma unroll
            for (int j = 0; j < 4; j++) {
                uint4 w;
                w.x = f2tf(pa[j].x); w.y = f2tf(pa[j].y);
                w.z = f2tf(pa[j].z); w.w = f2tf(pa[j].w);
                *(uint4*)&As[nb][tid][j * 4] = w;
            }
            Bs[nb][br][bc + 0]      = f2tf(pb[0].x);
            Bs[nb][br][bc + 1]      = f2tf(pb[0].y);
            Bs[nb][br][bc + 2]      = f2tf(pb[0].z);
            Bs[nb][br][bc + 3]      = f2tf(pb[0].w);
            Bs[nb][br][bc + 64]     = f2tf(pb[1].x);
            Bs[nb][br][bc + 65]     = f2tf(pb[1].y);
            Bs[nb][br][bc + 66]     = f2tf(pb[1].z);
            Bs[nb][br][bc + 67]     = f2tf(pb[1].w);
            Bs[nb][br + 8][bc + 0]  = f2tf(pb[2].x);
            Bs[nb][br + 8][bc + 1]  = f2tf(pb[2].y);
            Bs[nb][br + 8][bc + 2]  = f2tf(pb[2].z);
            Bs[nb][br + 8][bc + 3]  = f2tf(pb[2].w);
            Bs[nb][br + 8][bc + 64] = f2tf(pb[3].x);
            Bs[nb][br + 8][bc + 65] = f2tf(pb[3].y);
            Bs[nb][br + 8][bc + 66] = f2tf(pb[3].z);
            Bs[nb][br + 8][bc + 67] = f2tf(pb[3].w);
        }
        __syncthreads();
        buf ^= 1;
    }

    // Epilogue with bias
#pragma unroll
    for (int mt = 0; mt < 4; mt++) {
        const int r0 = bm + wm + mt * 16 + gid;
#pragma unroll
        for (int nt = 0; nt < 8; nt++) {
            const int col = bn + wn + nt * 8 + 2 * tig;
            const float bx = bias[col], by = bias[col + 1];
            float2 v0 = {acc[mt][nt][0] + bx, acc[mt][nt][1] + by};
            float2 v1 = {acc[mt][nt][2] + bx, acc[mt][nt][3] + by};
            *(float2*)(C + (size_t)r0 * N + col)       = v0;
            *(float2*)(C + (size_t)(r0 + 8) * N + col) = v1;
        }
    }
}

// ---------------------------------------------------------------------------
// Tensor-core flash attention with key-permuted V ("P as A-fragment").
// 128 q/block, 4 warps x 32 q. The PV mma consumes P's C-layout registers
// directly as an A-fragment; the key permutation this implies is folded into
// V's smem placement: key k -> slot sigma(k) = (k&56)|((k&1)<<2)|((k&7)>>1).
// Removes all 128 shfl + 64 sel per warp-ktile of the previous design.
// ---------------------------------------------------------------------------
__global__ __launch_bounds__(128) void flash_attn_tc(
    const float* __restrict__ qkv, float* __restrict__ y)
{
    __shared__ uint32_t ks[64][68];
    __shared__ uint32_t vst[64][68];   // [d][key-slot]

    const int tid  = threadIdx.x;
    const int lane = tid & 31;
    const int wid  = tid >> 5;
    const int gid  = lane >> 2;
    const int tig  = lane & 3;
    const int wq   = wid * 32;
    const int qt0  = (int)(gridDim.x - 1 - blockIdx.x) * 128;
    const int h    = blockIdx.y;
    const int b    = blockIdx.z;

    uint32_t qf[2][8][4];
#pragma unroll
    for (int mt = 0; mt < 2; mt++) {
        const float* q0 = qkv + ((size_t)(b * SEQ + qt0 + wq + mt * 16 + gid) * (3 * DM)) + h * HD;
        const float* q1 = q0 + (size_t)8 * 3 * DM;
#pragma unroll
        for (int kk = 0; kk < 8; kk++) {
            qf[mt][kk][0] = f2tf(q0[kk * 8 + tig]     * 0.125f);
            qf[mt][kk][1] = f2tf(q1[kk * 8 + tig]     * 0.125f);
            qf[mt][kk][2] = f2tf(q0[kk * 8 + tig + 4] * 0.125f);
            qf[mt][kk][3] = f2tf(q1[kk * 8 + tig + 4] * 0.125f);
        }
    }

    float o[2][8][4];
#pragma unroll
    for (int mt = 0; mt < 2; mt++)
#pragma unroll
        for (int nt = 0; nt < 8; nt++) {
            o[mt][nt][0] = 0.f; o[mt][nt][1] = 0.f;
            o[mt][nt][2] = 0.f; o[mt][nt][3] = 0.f;
        }
    float m[2][2] = {{-1e30f, -1e30f}, {-1e30f, -1e30f}};
    float l[2][2] = {{0.f, 0.f}, {0.f, 0.f}};

    const int ntiles = qt0 / 64 + 2;
    const int krow = tid & 63;
    const int kcb  = (tid >> 6) * 32;
    // V key-slot: sigma(k) = (k&56) | ((k&1)<<2) | ((k&7)>>1)
    const int kslot = (krow & 56) | ((krow & 1) << 2) | ((krow & 7) >> 1);

    for (int kt = 0; kt < ntiles; kt++) {
        const int kt0 = kt * 64;

        __syncthreads();
        {
            const float* kp = qkv + ((size_t)(b * SEQ + kt0 + krow) * (3 * DM)) + DM + h * HD + kcb;
            const float* vp = kp + DM;
#pragma unroll
            for (int j = 0; j < 32; j += 4) {
                float4 k4 = *(const float4*)(kp + j);
                float4 v4 = *(const float4*)(vp + j);
                uint4 w;
                w.x = f2tf(k4.x); w.y = f2tf(k4.y); w.z = f2tf(k4.z); w.w = f2tf(k4.w);
                *(uint4*)&ks[krow][kcb + j] = w;
                vst[kcb + j + 0][kslot] = f2tf(v4.x);
                vst[kcb + j + 1][kslot] = f2tf(v4.y);
                vst[kcb + j + 2][kslot] = f2tf(v4.z);
                vst[kcb + j + 3][kslot] = f2tf(v4.w);
            }
        }
        __syncthreads();

        if (kt0 > qt0 + wq + 31) continue;

        float acc[2][8][4];
#pragma unroll
        for (int mt = 0; mt < 2; mt++)
#pragma unroll
            for (int nt = 0; nt < 8; nt++) {
                acc[mt][nt][0] = 0.f; acc[mt][nt][1] = 0.f;
                acc[mt][nt][2] = 0.f; acc[mt][nt][3] = 0.f;
            }
#pragma unroll
        for (int kk = 0; kk < 8; kk++) {
            uint32_t bf0[8], bf1[8];
#pragma unroll
            for (int nt = 0; nt < 8; nt++) {
                bf0[nt] = ks[nt * 8 + gid][kk * 8 + tig];
                bf1[nt] = ks[nt * 8 + gid][kk * 8 + tig + 4];
            }
#pragma unroll
            for (int mt = 0; mt < 2; mt++)
#pragma unroll
                for (int nt = 0; nt < 8; nt++)
                    MMA_TF32(acc[mt][nt], qf[mt][kk], bf0[nt], bf1[nt]);
        }

#pragma unroll
        for (int mt = 0; mt < 2; mt++) {
            if (kt0 + 63 > qt0 + wq + mt * 16) {
                const int r0 = qt0 + wq + mt * 16 + gid, r1 = r0 + 8;
#pragma unroll
                for (int nt = 0; nt < 8; nt++) {
                    const int c = kt0 + nt * 8 + 2 * tig;
                    if (c     > r0) acc[mt][nt][0] = -1e30f;
                    if (c + 1 > r0) acc[mt][nt][1] = -1e30f;
                    if (c     > r1) acc[mt][nt][2] = -1e30f;
                    if (c + 1 > r1) acc[mt][nt][3] = -1e30f;
                }
            }
        }

#pragma unroll
        for (int mt = 0; mt < 2; mt++) {
            float mt0 = -1e30f, mt1 = -1e30f;
#pragma unroll
            for (int nt = 0; nt < 8; nt++) {
                mt0 = fmaxf(mt0, fmaxf(acc[mt][nt][0], acc[mt][nt][1]));
                mt1 = fmaxf(mt1, fmaxf(acc[mt][nt][2], acc[mt][nt][3]));
            }
            mt0 = fmaxf(mt0, __shfl_xor_sync(0xffffffffu, mt0, 1));
            mt0 = fmaxf(mt0, __shfl_xor_sync(0xffffffffu, mt0, 2));
            mt1 = fmaxf(mt1, __shfl_xor_sync(0xffffffffu, mt1, 1));
            mt1 = fmaxf(mt1, __shfl_xor_sync(0xffffffffu, mt1, 2));

            const float mn0 = fmaxf(m[mt][0], mt0), mn1 = fmaxf(m[mt][1], mt1);
            const float cr0 = __expf(m[mt][0] - mn0), cr1 = __expf(m[mt][1] - mn1);
            m[mt][0] = mn0; m[mt][1] = mn1;
            l[mt][0] *= cr0; l[mt][1] *= cr1;

            float s0 = 0.f, s1 = 0.f;
#pragma unroll
            for (int nt = 0; nt < 8; nt++) {
                const float p0 = __expf(acc[mt][nt][0] - mn0);
                const float p1 = __expf(acc[mt][nt][1] - mn0);
                const float p2 = __expf(acc[mt][nt][2] - mn1);
                const float p3 = __expf(acc[mt][nt][3] - mn1);
                s0 += p0 + p1;
                s1 += p2 + p3;
                o[mt][nt][0] *= cr0; o[mt][nt][1] *= cr0;
                o[mt][nt][2] *= cr1; o[mt][nt][3] *= cr1;
                acc[mt][nt][0] = __uint_as_float(f2tf(p0));
                acc[mt][nt][1] = __uint_as_float(f2tf(p1));
                acc[mt][nt][2] = __uint_as_float(f2tf(p2));
                acc[mt][nt][3] = __uint_as_float(f2tf(p3));
            }
            s0 += __shfl_xor_sync(0xffffffffu, s0, 1);
            s0 += __shfl_xor_sync(0xffffffffu, s0, 2);
            s1 += __shfl_xor_sync(0xffffffffu, s1, 1);
            s1 += __shfl_xor_sync(0xffffffffu, s1, 2);
            l[mt][0] += s0; l[mt][1] += s1;
        }

        // O += P V : P's C-layout registers ARE the A-fragment under the
        // key permutation baked into vst. A regs = {p0, p2, p1, p3}.
#pragma unroll
        for (int kk = 0; kk < 8; kk++) {
#pragma unroll
            for (int nt = 0; nt < 8; nt++) {
                const uint32_t b0 = vst[nt * 8 + gid][kk * 8 + tig];
                const uint32_t b1 = vst[nt * 8 + gid][kk * 8 + tig + 4];
#pragma unroll
                for (int mt = 0; mt < 2; mt++)
                    MMA_TF32_A4(o[mt][nt],
                                __float_as_uint(acc[mt][kk][0]),
                                __float_as_uint(acc[mt][kk][2]),
                                __float_as_uint(acc[mt][kk][1]),
                                __float_as_uint(acc[mt][kk][3]),
                                b0, b1);
            }
        }
    }

#pragma unroll
    for (int mt = 0; mt < 2; mt++) {
        const float i0 = 1.f / l[mt][0], i1 = 1.f / l[mt][1];
        float* y0 = y + (size_t)(b * SEQ + qt0 + wq + mt * 16 + gid) * DM + h * HD;
        float* y1 = y0 + (size_t)8 * DM;
#pragma unroll
        for (int nt = 0; nt < 8; nt++) {
            const int c = nt * 8 + 2 * tig;
            float2 w0 = {o[mt][nt][0] * i0, o[mt][nt][1] * i0};
            float2 w1 = {o[mt][nt][2] * i1, o[mt][nt][3] * i1};
            *(float2*)(y0 + c) = w0;
            *(float2*)(y1 + c) = w1;
        }
    }
}

// ---------------------------------------------------------------------------
// Launch
// ---------------------------------------------------------------------------
extern "C" void kernel_launch(void* const* d_in, const int* in_sizes, int n_in,
                              void* d_out, int out_size)
{
    (void)in_sizes; (void)n_in; (void)out_size;
    const float* x      = (const float*)d_in[0];
    const float* w_qkv  = (const float*)d_in[1];
    const float* b_qkv  = (const float*)d_in[2];
    const float* w_proj = (const float*)d_in[3];
    const float* b_proj = (const float*)d_in[4];
    float* out = (float*)d_out;

    float* qkv = nullptr;
    float* y   = nullptr;
    cudaGetSymbolAddress((void**)&qkv, g_qkv);
    cudaGetSymbolAddress((void**)&y,   g_y);

    // 1) QKV projection: [8192,1024] @ [1024,3072] + b
    tf32_gemm_bias<<<dim3(3 * DM / 128, M_ROWS / 128), 128>>>(
        x, w_qkv, b_qkv, qkv, M_ROWS, 3 * DM, DM);

    // 2) Causal flash attention (128 queries per block, 4 warps)
    flash_attn_tc<<<dim3(SEQ / 128, NH, BATCH), 128>>>(qkv, y);

    // 3) Output projection: [8192,1024] @ [1024,1024] + b
    tf32_gemm_bias<<<dim3(DM / 128, M_ROWS / 128), 128>>>(
        y, w_proj, b_proj, out, M_ROWS, DM, DM);
}

// round 16
// speedup vs baseline: 1.1882x; 1.0113x over previous
#include <cuda_runtime.h>
#include <cuda_bf16.h>
#include <cstdint>

// Problem constants
#define BATCH 4
#define SEQ   2048
#define DM    1024
#define NH    16
#define HD    64
#define M_ROWS (BATCH*SEQ)   // 8192

// Scratch (device globals; no allocation allowed)
__device__ float g_qkv[(size_t)M_ROWS * 3 * DM];   // [B*T, 3*C] (sel, head, hd)
__device__ float g_y[(size_t)M_ROWS * DM];         // [B*T, C]

__device__ __forceinline__ uint32_t f2tf(float f) {
    uint32_t u;
    asm("cvt.rna.tf32.f32 %0, %1;" : "=r"(u) : "f"(f));
    return u;
}

__device__ __forceinline__ uint32_t smem_u32(const void* p) {
    uint32_t a;
    asm("{ .reg .u64 t; cvta.to.shared.u64 t, %1; cvt.u32.u64 %0, t; }"
        : "=r"(a) : "l"(p));
    return a;
}

#define MMA_TF32(acc, a, b0v, b1v)                                              \
    asm volatile(                                                               \
        "mma.sync.aligned.m16n8k8.row.col.f32.tf32.tf32.f32 "                   \
        "{%0,%1,%2,%3}, {%4,%5,%6,%7}, {%8,%9}, {%0,%1,%2,%3};"                 \
        : "+f"(acc[0]), "+f"(acc[1]), "+f"(acc[2]), "+f"(acc[3])                \
        : "r"(a[0]), "r"(a[1]), "r"(a[2]), "r"(a[3]), "r"(b0v), "r"(b1v))

// Variant taking 4 explicit A regs (for P-as-A-fragment renaming)
#define MMA_TF32_A4(acc, a0, a1, a2, a3, b0v, b1v)                              \
    asm volatile(                                                               \
        "mma.sync.aligned.m16n8k8.row.col.f32.tf32.tf32.f32 "                   \
        "{%0,%1,%2,%3}, {%4,%5,%6,%7}, {%8,%9}, {%0,%1,%2,%3};"                 \
        : "+f"(acc[0]), "+f"(acc[1]), "+f"(acc[2]), "+f"(acc[3])                \
        : "r"(a0), "r"(a1), "r"(a2), "r"(a3), "r"(b0v), "r"(b1v))

#define LDSM_X4(r, addr)                                                        \
    asm volatile(                                                               \
        "ldmatrix.sync.aligned.m8n8.x4.shared.b16 {%0,%1,%2,%3}, [%4];"         \
        : "=r"((r)[0]), "=r"((r)[1]), "=r"((r)[2]), "=r"((r)[3])                \
        : "r"(addr))

#define TFS 136   // B smem row stride (8 mod 32 -> conflict-free quad frag loads)
#define AST 20    // A smem row stride (16B aligned; LDSM bank-distinct)

// 0.125 * log2(e): QK^T logits produced directly in log2 domain
#define QSCALE 0.18033688011112042f

// ---------------------------------------------------------------------------
// TF32 GEMM with bias (r12/r15, measured best 415.7us): 128x128 tile, BK=16
// double-buffered, 128 thr (4 warps 2x2), warp tile 64x64, 2 CTAs/SM.
// A frags via ldmatrix.x4, B frags scalar (conflict-free). cvt at store.
// ---------------------------------------------------------------------------
__global__ __launch_bounds__(128, 2) void tf32_gemm_bias(
    const float* __restrict__ A, const float* __restrict__ B,
    const float* __restrict__ bias, float* __restrict__ C,
    int M, int N, int K)
{
    __shared__ uint32_t As[2][128][AST];   // [buf][row][k]  (10240 B per buf)
    __shared__ uint32_t Bs[2][16][TFS];    // [buf][k][col]

    const int tid  = threadIdx.x;
    const int lane = tid & 31;
    const int wid  = tid >> 5;
    const int gid  = lane >> 2;
    const int tig  = lane & 3;
    const int wm   = (wid & 1) * 64;
    const int wn   = (wid >> 1) * 64;
    const int bm   = blockIdx.y * 128;
    const int bn   = blockIdx.x * 128;

    const int br = tid >> 4;          // 0..7
    const int bc = (tid & 15) * 4;    // 0..60

    const float* Ap = A + (size_t)(bm + tid) * K;
    const float* Bp = B + (size_t)br * N + bn + bc;

    const uint32_t aLdsm = smem_u32(&As[0][0][0]) +
        (uint32_t)(((wm + (lane & 15)) * AST + ((lane >> 4) << 2)) * 4);

    float acc[4][8][4];
#pragma unroll
    for (int mt = 0; mt < 4; mt++)
#pragma unroll
        for (int nt = 0; nt < 8; nt++)
#pragma unroll
            for (int i = 0; i < 4; i++) acc[mt][nt][i] = 0.f;

    const int ntiles = K / 16;
    float4 pa[4], pb[4];

    // Preload tile 0 -> buf 0
    {
#pragma unroll
        for (int j = 0; j < 4; j++) pa[j] = ((const float4*)Ap)[j];
        pb[0] = *(const float4*)(Bp);
        pb[1] = *(const float4*)(Bp + 64);
        pb[2] = *(const float4*)(Bp + (size_t)8 * N);
        pb[3] = *(const float4*)(Bp + (size_t)8 * N + 64);
#pragma unroll
        for (int j = 0; j < 4; j++) {
            uint4 w;
            w.x = f2tf(pa[j].x); w.y = f2tf(pa[j].y);
            w.z = f2tf(pa[j].z); w.w = f2tf(pa[j].w);
            *(uint4*)&As[0][tid][j * 4] = w;
        }
        Bs[0][br][bc + 0]      = f2tf(pb[0].x);
        Bs[0][br][bc + 1]      = f2tf(pb[0].y);
        Bs[0][br][bc + 2]      = f2tf(pb[0].z);
        Bs[0][br][bc + 3]      = f2tf(pb[0].w);
        Bs[0][br][bc + 64]     = f2tf(pb[1].x);
        Bs[0][br][bc + 65]     = f2tf(pb[1].y);
        Bs[0][br][bc + 66]     = f2tf(pb[1].z);
        Bs[0][br][bc + 67]     = f2tf(pb[1].w);
        Bs[0][br + 8][bc + 0]  = f2tf(pb[2].x);
        Bs[0][br + 8][bc + 1]  = f2tf(pb[2].y);
        Bs[0][br + 8][bc + 2]  = f2tf(pb[2].z);
        Bs[0][br + 8][bc + 3]  = f2tf(pb[2].w);
        Bs[0][br + 8][bc + 64] = f2tf(pb[3].x);
        Bs[0][br + 8][bc + 65] = f2tf(pb[3].y);
        Bs[0][br + 8][bc + 66] = f2tf(pb[3].z);
        Bs[0][br + 8][bc + 67] = f2tf(pb[3].w);
    }
    __syncthreads();

    int buf = 0;
    for (int t = 0; t < ntiles; t++) {
        if (t + 1 < ntiles) {
            const int k0 = (t + 1) * 16;
            const float* ap = Ap + k0;
            const float* bp = Bp + (size_t)k0 * N;
#pragma unroll
            for (int j = 0; j < 4; j++) pa[j] = ((const float4*)ap)[j];
            pb[0] = *(const float4*)(bp);
            pb[1] = *(const float4*)(bp + 64);
            pb[2] = *(const float4*)(bp + (size_t)8 * N);
            pb[3] = *(const float4*)(bp + (size_t)8 * N + 64);
        }

        const uint32_t aBufAddr = aLdsm + (uint32_t)(buf * 10240);
#pragma unroll
        for (int kk = 0; kk < 16; kk += 8) {
            uint32_t af[4][4], bf[8][2];
            LDSM_X4(af[0], aBufAddr + kk * 4);
            LDSM_X4(af[1], aBufAddr + 1 * 1280 + kk * 4);
            LDSM_X4(af[2], aBufAddr + 2 * 1280 + kk * 4);
            LDSM_X4(af[3], aBufAddr + 3 * 1280 + kk * 4);
#pragma unroll
            for (int nt = 0; nt < 8; nt++) {
                const int c = wn + nt * 8 + gid;
                bf[nt][0] = Bs[buf][kk + tig][c];
                bf[nt][1] = Bs[buf][kk + tig + 4][c];
            }
#pragma unroll
            for (int mt = 0; mt < 4; mt++)
#pragma unroll
                for (int nt = 0; nt < 8; nt++)
                    MMA_TF32(acc[mt][nt], af[mt], bf[nt][0], bf[nt][1]);
        }

        if (t + 1 < ntiles) {
            const int nb = buf ^ 1;
#pragma unroll
            for (int j = 0; j < 4; j++) {
                uint4 w;
                w.x = f2tf(pa[j].x); w.y = f2tf(pa[j].y);
                w.z = f2tf(pa[j].z); w.w = f2tf(pa[j].w);
                *(uint4*)&As[nb][tid][j * 4] = w;
            }
            Bs[nb][br][bc + 0]      = f2tf(pb[0].x);
            Bs[nb][br][bc + 1]      = f2tf(pb[0].y);
            Bs[nb][br][bc + 2]      = f2tf(pb[0].z);
            Bs[nb][br][bc + 3]      = f2tf(pb[0].w);
            Bs[nb][br][bc + 64]     = f2tf(pb[1].x);
            Bs[nb][br][bc + 65]     = f2tf(pb[1].y);
            Bs[nb][br][bc + 66]     = f2tf(pb[1].z);
            Bs[nb][br][bc + 67]     = f2tf(pb[1].w);
            Bs[nb][br + 8][bc + 0]  = f2tf(pb[2].x);
            Bs[nb][br + 8][bc + 1]  = f2tf(pb[2].y);
            Bs[nb][br + 8][bc + 2]  = f2tf(pb[2].z);
            Bs[nb][br + 8][bc + 3]  = f2tf(pb[2].w);
            Bs[nb][br + 8][bc + 64] = f2tf(pb[3].x);
            Bs[nb][br + 8][bc + 65] = f2tf(pb[3].y);
            Bs[nb][br + 8][bc + 66] = f2tf(pb[3].z);
            Bs[nb][br + 8][bc + 67] = f2tf(pb[3].w);
        }
        __syncthreads();
        buf ^= 1;
    }

    // Epilogue with bias
#pragma unroll
    for (int mt = 0; mt < 4; mt++) {
        const int r0 = bm + wm + mt * 16 + gid;
#pragma unroll
        for (int nt = 0; nt < 8; nt++) {
            const int col = bn + wn + nt * 8 + 2 * tig;
            const float bx = bias[col], by = bias[col + 1];
            float2 v0 = {acc[mt][nt][0] + bx, acc[mt][nt][1] + by};
            float2 v1 = {acc[mt][nt][2] + bx, acc[mt][nt][3] + by};
            *(float2*)(C + (size_t)r0 * N + col)       = v0;
            *(float2*)(C + (size_t)(r0 + 8) * N + col) = v1;
        }
    }
}

// ---------------------------------------------------------------------------
// Tensor-core flash attention, key-permuted V, exp2-domain softmax, raw-V/P.
// 128 q/block, 4 warps x 32 q.
//  - QK^T logits in log2 domain (log2e folded into Q scale) -> exp2f = bare
//    MUFU, no FMUL per exp.
//  - V stored WITHOUT cvt (HW truncates tf32 operand mantissa in HMMA).
//  - P fed to PV mma as raw fp32 exp2 results (no cvt), via the key-permuted
//    "P as A-fragment" renaming {p0,p2,p1,p3}.
// ---------------------------------------------------------------------------
__global__ __launch_bounds__(128) void flash_attn_tc(
    const float* __restrict__ qkv, float* __restrict__ y)
{
    __shared__ uint32_t ks[64][68];
    __shared__ uint32_t vst[64][68];   // [d][key-slot], raw fp32 bits

    const int tid  = threadIdx.x;
    const int lane = tid & 31;
    const int wid  = tid >> 5;
    const int gid  = lane >> 2;
    const int tig  = lane & 3;
    const int wq   = wid * 32;
    const int qt0  = (int)(gridDim.x - 1 - blockIdx.x) * 128;
    const int h    = blockIdx.y;
    const int b    = blockIdx.z;

    uint32_t qf[2][8][4];
#pragma unroll
    for (int mt = 0; mt < 2; mt++) {
        const float* q0 = qkv + ((size_t)(b * SEQ + qt0 + wq + mt * 16 + gid) * (3 * DM)) + h * HD;
        const float* q1 = q0 + (size_t)8 * 3 * DM;
#pragma unroll
        for (int kk = 0; kk < 8; kk++) {
            qf[mt][kk][0] = f2tf(q0[kk * 8 + tig]     * QSCALE);
            qf[mt][kk][1] = f2tf(q1[kk * 8 + tig]     * QSCALE);
            qf[mt][kk][2] = f2tf(q0[kk * 8 + tig + 4] * QSCALE);
            qf[mt][kk][3] = f2tf(q1[kk * 8 + tig + 4] * QSCALE);
        }
    }

    float o[2][8][4];
#pragma unroll
    for (int mt = 0; mt < 2; mt++)
#pragma unroll
        for (int nt = 0; nt < 8; nt++) {
            o[mt][nt][0] = 0.f; o[mt][nt][1] = 0.f;
            o[mt][nt][2] = 0.f; o[mt][nt][3] = 0.f;
        }
    float m[2][2] = {{-1e30f, -1e30f}, {-1e30f, -1e30f}};
    float l[2][2] = {{0.f, 0.f}, {0.f, 0.f}};

    const int ntiles = qt0 / 64 + 2;
    const int krow = tid & 63;
    const int kcb  = (tid >> 6) * 32;
    // V key-slot: sigma(k) = (k&56) | ((k&1)<<2) | ((k&7)>>1)
    const int kslot = (krow & 56) | ((krow & 1) << 2) | ((krow & 7) >> 1);

    for (int kt = 0; kt < ntiles; kt++) {
        const int kt0 = kt * 64;

        __syncthreads();
        {
            const float* kp = qkv + ((size_t)(b * SEQ + kt0 + krow) * (3 * DM)) + DM + h * HD + kcb;
            const float* vp = kp + DM;
#pragma unroll
            for (int j = 0; j < 32; j += 4) {
                float4 k4 = *(const float4*)(kp + j);
                uint4 v4 = *(const uint4*)(vp + j);     // raw bits, no cvt
                uint4 w;
                w.x = f2tf(k4.x); w.y = f2tf(k4.y); w.z = f2tf(k4.z); w.w = f2tf(k4.w);
                *(uint4*)&ks[krow][kcb + j] = w;
                vst[kcb + j + 0][kslot] = v4.x;
                vst[kcb + j + 1][kslot] = v4.y;
                vst[kcb + j + 2][kslot] = v4.z;
                vst[kcb + j + 3][kslot] = v4.w;
            }
        }
        __syncthreads();

        if (kt0 > qt0 + wq + 31) continue;

        float acc[2][8][4];
#pragma unroll
        for (int mt = 0; mt < 2; mt++)
#pragma unroll
            for (int nt = 0; nt < 8; nt++) {
                acc[mt][nt][0] = 0.f; acc[mt][nt][1] = 0.f;
                acc[mt][nt][2] = 0.f; acc[mt][nt][3] = 0.f;
            }
#pragma unroll
        for (int kk = 0; kk < 8; kk++) {
            uint32_t bf0[8], bf1[8];
#pragma unroll
            for (int nt = 0; nt < 8; nt++) {
                bf0[nt] = ks[nt * 8 + gid][kk * 8 + tig];
                bf1[nt] = ks[nt * 8 + gid][kk * 8 + tig + 4];
            }
#pragma unroll
            for (int mt = 0; mt < 2; mt++)
#pragma unroll
                for (int nt = 0; nt < 8; nt++)
                    MMA_TF32(acc[mt][nt], qf[mt][kk], bf0[nt], bf1[nt]);
        }

#pragma unroll
        for (int mt = 0; mt < 2; mt++) {
            if (kt0 + 63 > qt0 + wq + mt * 16) {
                const int r0 = qt0 + wq + mt * 16 + gid, r1 = r0 + 8;
#pragma unroll
                for (int nt = 0; nt < 8; nt++) {
                    const int c = kt0 + nt * 8 + 2 * tig;
                    if (c     > r0) acc[mt][nt][0] = -1e30f;
                    if (c + 1 > r0) acc[mt][nt][1] = -1e30f;
                    if (c     > r1) acc[mt][nt][2] = -1e30f;
                    if (c + 1 > r1) acc[mt][nt][3] = -1e30f;
                }
            }
        }

#pragma unroll
        for (int mt = 0; mt < 2; mt++) {
            float mt0 = -1e30f, mt1 = -1e30f;
#pragma unroll
            for (int nt = 0; nt < 8; nt++) {
                mt0 = fmaxf(mt0, fmaxf(acc[mt][nt][0], acc[mt][nt][1]));
                mt1 = fmaxf(mt1, fmaxf(acc[mt][nt][2], acc[mt][nt][3]));
            }
            mt0 = fmaxf(mt0, __shfl_xor_sync(0xffffffffu, mt0, 1));
            mt0 = fmaxf(mt0, __shfl_xor_sync(0xffffffffu, mt0, 2));
            mt1 = fmaxf(mt1, __shfl_xor_sync(0xffffffffu, mt1, 1));
            mt1 = fmaxf(mt1, __shfl_xor_sync(0xffffffffu, mt1, 2));

            const float mn0 = fmaxf(m[mt][0], mt0), mn1 = fmaxf(m[mt][1], mt1);
            const float cr0 = exp2f(m[mt][0] - mn0), cr1 = exp2f(m[mt][1] - mn1);
            m[mt][0] = mn0; m[mt][1] = mn1;
            l[mt][0] *= cr0; l[mt][1] *= cr1;

            float s0 = 0.f, s1 = 0.f;
#pragma unroll
            for (int nt = 0; nt < 8; nt++) {
                const float p0 = exp2f(acc[mt][nt][0] - mn0);
                const float p1 = exp2f(acc[mt][nt][1] - mn0);
                const float p2 = exp2f(acc[mt][nt][2] - mn1);
                const float p3 = exp2f(acc[mt][nt][3] - mn1);
                s0 += p0 + p1;
                s1 += p2 + p3;
                o[mt][nt][0] *= cr0; o[mt][nt][1] *= cr0;
                o[mt][nt][2] *= cr1; o[mt][nt][3] *= cr1;
                acc[mt][nt][0] = p0;   // raw fp32; HMMA truncates to tf32
                acc[mt][nt][1] = p1;
                acc[mt][nt][2] = p2;
                acc[mt][nt][3] = p3;
            }
            s0 += __shfl_xor_sync(0xffffffffu, s0, 1);
            s0 += __shfl_xor_sync(0xffffffffu, s0, 2);
            s1 += __shfl_xor_sync(0xffffffffu, s1, 1);
            s1 += __shfl_xor_sync(0xffffffffu, s1, 2);
            l[mt][0] += s0; l[mt][1] += s1;
        }

        // O += P V : P's C-layout regs as A-fragment under key-permuted V.
#pragma unroll
        for (int kk = 0; kk < 8; kk++) {
#pragma unroll
            for (int nt = 0; nt < 8; nt++) {
                const uint32_t b0 = vst[nt * 8 + gid][kk * 8 + tig];
                const uint32_t b1 = vst[nt * 8 + gid][kk * 8 + tig + 4];
#pragma unroll
                for (int mt = 0; mt < 2; mt++)
                    MMA_TF32_A4(o[mt][nt],
                                __float_as_uint(acc[mt][kk][0]),
                                __float_as_uint(acc[mt][kk][2]),
                                __float_as_uint(acc[mt][kk][1]),
                                __float_as_uint(acc[mt][kk][3]),
                                b0, b1);
            }
        }
    }

#pragma unroll
    for (int mt = 0; mt < 2; mt++) {
        const float i0 = 1.f / l[mt][0], i1 = 1.f / l[mt][1];
        float* y0 = y + (size_t)(b * SEQ + qt0 + wq + mt * 16 + gid) * DM + h * HD;
        float* y1 = y0 + (size_t)8 * DM;
#pragma unroll
        for (int nt = 0; nt < 8; nt++) {
            const int c = nt * 8 + 2 * tig;
            float2 w0 = {o[mt][nt][0] * i0, o[mt][nt][1] * i0};
            float2 w1 = {o[mt][nt][2] * i1, o[mt][nt][3] * i1};
            *(float2*)(y0 + c) = w0;
            *(float2*)(y1 + c) = w1;
        }
    }
}

// ---------------------------------------------------------------------------
// Launch
// ---------------------------------------------------------------------------
extern "C" void kernel_launch(void* const* d_in, const int* in_sizes, int n_in,
                              void* d_out, int out_size)
{
    (void)in_sizes; (void)n_in; (void)out_size;
    const float* x      = (const float*)d_in[0];
    const float* w_qkv  = (const float*)d_in[1];
    const float* b_qkv  = (const float*)d_in[2];
    const float* w_proj = (const float*)d_in[3];
    const float* b_proj = (const float*)d_in[4];
    float* out = (float*)d_out;

    float* qkv = nullptr;
    float* y   = nullptr;
    cudaGetSymbolAddress((void**)&qkv, g_qkv);
    cudaGetSymbolAddress((void**)&y,   g_y);

    // 1) QKV projection: [8192,1024] @ [1024,3072] + b
    tf32_gemm_bias<<<dim3(3 * DM / 128, M_ROWS / 128), 128>>>(
        x, w_qkv, b_qkv, qkv, M_ROWS, 3 * DM, DM);

    // 2) Causal flash attention (128 queries per block, 4 warps)
    flash_attn_tc<<<dim3(SEQ / 128, NH, BATCH), 128>>>(qkv, y);

    // 3) Output projection: [8192,1024] @ [1024,1024] + b
    tf32_gemm_bias<<<dim3(DM / 128, M_ROWS / 128), 128>>>(
        y, w_proj, b_proj, out, M_ROWS, DM, DM);
}